// round 1
// baseline (speedup 1.0000x reference)
#include <cuda_runtime.h>
#include <cuda_bf16.h>

#define BATCH 32
#define SEQ   4096
#define EMBED 512
#define HID   256
#define OUTD  128

__device__ float g_xm[SEQ * EMBED];    // batch-mean  [4096][512]
__device__ float g_cur[SEQ * HID];     // currents    [4096][256]

// ---------------------------------------------------------------------------
// Kernel 1: batch mean over B=32.  x: [32][4096][512] -> xm: [4096][512]
// ---------------------------------------------------------------------------
__global__ void snn_mean_kernel(const float* __restrict__ x) {
    const int NF4 = (SEQ * EMBED) / 4;               // 524288 float4 per batch
    int i = blockIdx.x * blockDim.x + threadIdx.x;   // float4 index
    if (i >= NF4) return;
    const float4* x4 = reinterpret_cast<const float4*>(x);
    float sx = 0.f, sy = 0.f, sz = 0.f, sw = 0.f;
#pragma unroll
    for (int b = 0; b < BATCH; b++) {
        float4 v = x4[(size_t)b * NF4 + i];
        sx += v.x; sy += v.y; sz += v.z; sw += v.w;
    }
    const float inv = 1.0f / 32.0f;
    float4 r; r.x = sx * inv; r.y = sy * inv; r.z = sz * inv; r.w = sw * inv;
    reinterpret_cast<float4*>(g_xm)[i] = r;
}

// ---------------------------------------------------------------------------
// Kernel 2: SGEMM  currents[4096][256] = xm[4096][512] @ W1[512][256]
// 64x64 block tile, 32 k-chunk, 4x4 micro-tile, 256 threads.
// ---------------------------------------------------------------------------
#define BM 64
#define BN 64
#define BK 32

__global__ void snn_gemm_kernel(const float* __restrict__ W1) {
    __shared__ float sA[BK][BM];   // k-major A tile
    __shared__ float sB[BK][BN];

    const int tid = threadIdx.x;
    const int s0 = blockIdx.y * BM;
    const int h0 = blockIdx.x * BN;
    const int ty = tid >> 4;       // 0..15
    const int tx = tid & 15;       // 0..15

    float acc[4][4];
#pragma unroll
    for (int i = 0; i < 4; i++)
#pragma unroll
        for (int j = 0; j < 4; j++) acc[i][j] = 0.f;

    for (int k0 = 0; k0 < EMBED; k0 += BK) {
        // Load A tile (64 rows x 32 k): 512 float4, 2 per thread, transpose to k-major
#pragma unroll
        for (int l = 0; l < 2; l++) {
            int f   = tid + l * 256;         // 0..511
            int row = f >> 3;                // 8 float4 per row
            int c4  = f & 7;
            float4 v = *reinterpret_cast<const float4*>(
                &g_xm[(size_t)(s0 + row) * EMBED + k0 + c4 * 4]);
            sA[c4 * 4 + 0][row] = v.x;
            sA[c4 * 4 + 1][row] = v.y;
            sA[c4 * 4 + 2][row] = v.z;
            sA[c4 * 4 + 3][row] = v.w;
        }
        // Load B tile (32 k x 64 h): 512 float4, 2 per thread
#pragma unroll
        for (int l = 0; l < 2; l++) {
            int f  = tid + l * 256;
            int r  = f >> 4;                 // 16 float4 per row
            int c4 = f & 15;
            *reinterpret_cast<float4*>(&sB[r][c4 * 4]) =
                *reinterpret_cast<const float4*>(&W1[(size_t)(k0 + r) * HID + h0 + c4 * 4]);
        }
        __syncthreads();

#pragma unroll
        for (int k = 0; k < BK; k++) {
            float4 a = *reinterpret_cast<float4*>(&sA[k][ty * 4]);
            float4 b = *reinterpret_cast<float4*>(&sB[k][tx * 4]);
            acc[0][0] += a.x * b.x; acc[0][1] += a.x * b.y; acc[0][2] += a.x * b.z; acc[0][3] += a.x * b.w;
            acc[1][0] += a.y * b.x; acc[1][1] += a.y * b.y; acc[1][2] += a.y * b.z; acc[1][3] += a.y * b.w;
            acc[2][0] += a.z * b.x; acc[2][1] += a.z * b.y; acc[2][2] += a.z * b.z; acc[2][3] += a.z * b.w;
            acc[3][0] += a.w * b.x; acc[3][1] += a.w * b.y; acc[3][2] += a.w * b.z; acc[3][3] += a.w * b.w;
        }
        __syncthreads();
    }

#pragma unroll
    for (int i = 0; i < 4; i++) {
        float4 v;
        v.x = acc[i][0]; v.y = acc[i][1]; v.z = acc[i][2]; v.w = acc[i][3];
        *reinterpret_cast<float4*>(
            &g_cur[(size_t)(s0 + ty * 4 + i) * HID + h0 + tx * 4]) = v;
    }
}

// ---------------------------------------------------------------------------
// Kernel 3: per-h LIF scan over S=4096 + output projection + batch broadcast.
// One block, 256 threads (thread == hidden unit).
// ---------------------------------------------------------------------------
#define DECAY      0.95f
#define THRESHOLD  1.0f
#define GROUP      32           // steps per prefetch group
#define NGROUPS    (SEQ / GROUP)

__global__ void __launch_bounds__(256, 1)
snn_scan_out_kernel(const float* __restrict__ W2, float* __restrict__ out) {
    __shared__ float scnt[HID];
    const int h = threadIdx.x;

    float mem = 0.f, refr = 0.f, cnt = 0.f;
    float bufA[GROUP], bufB[GROUP];

#pragma unroll
    for (int j = 0; j < GROUP; j++) bufA[j] = g_cur[(size_t)j * HID + h];

#define STEP(ICV)                                                   \
    do {                                                            \
        float ice = (refr <= 0.0f) ? (ICV) : 0.0f;                  \
        mem = fmaf(DECAY, mem, ice);                                \
        bool sp = (mem >= THRESHOLD);                               \
        cnt += sp ? 1.0f : 0.0f;                                    \
        refr = sp ? 2.0f : fmaxf(refr - 1.0f, 0.0f);                \
        mem = sp ? 0.0f : mem;                                      \
    } while (0)

    for (int g = 0; g < NGROUPS; g += 2) {
        // prefetch group g+1 while processing g
#pragma unroll
        for (int j = 0; j < GROUP; j++)
            bufB[j] = g_cur[(size_t)((g + 1) * GROUP + j) * HID + h];
#pragma unroll
        for (int j = 0; j < GROUP; j++) STEP(bufA[j]);

        if (g + 2 < NGROUPS) {
#pragma unroll
            for (int j = 0; j < GROUP; j++)
                bufA[j] = g_cur[(size_t)((g + 2) * GROUP + j) * HID + h];
        }
#pragma unroll
        for (int j = 0; j < GROUP; j++) STEP(bufB[j]);
    }
#undef STEP

    scnt[h] = cnt;
    __syncthreads();

    if (h < OUTD) {
        float a = 0.f;
#pragma unroll 8
        for (int k = 0; k < HID; k++)
            a += scnt[k] * W2[(size_t)k * OUTD + h];
        a *= (1.0f / (float)SEQ);
#pragma unroll
        for (int b = 0; b < BATCH; b++)
            out[(size_t)b * OUTD + h] = a;
    }
}

// ---------------------------------------------------------------------------
extern "C" void kernel_launch(void* const* d_in, const int* in_sizes, int n_in,
                              void* d_out, int out_size) {
    const float* x  = (const float*)d_in[0];   // [32][4096][512]
    const float* w1 = (const float*)d_in[1];   // [512][256]
    const float* w2 = (const float*)d_in[2];   // [256][128]
    float* out = (float*)d_out;                // [32][128]

    snn_mean_kernel<<<(SEQ * EMBED / 4 + 255) / 256, 256>>>(x);
    snn_gemm_kernel<<<dim3(HID / BN, SEQ / BM), 256>>>(w1);
    snn_scan_out_kernel<<<1, 256>>>(w2, out);
}

// round 2
// speedup vs baseline: 1.1908x; 1.1908x over previous
#include <cuda_runtime.h>
#include <cuda_bf16.h>

#define BATCH 32
#define SEQ   4096
#define EMBED 512
#define HID   256
#define OUTD  128

__device__ float g_xm[SEQ * EMBED];     // batch-mean  [4096][512]
__device__ float g_curT[HID * SEQ];     // currents TRANSPOSED [256][4096]
__device__ float g_cnt[HID];            // spike counts per hidden unit

// ---------------------------------------------------------------------------
// Kernel 1: batch mean over B=32.  x: [32][4096][512] -> xm: [4096][512]
// ---------------------------------------------------------------------------
__global__ void snn_mean_kernel(const float* __restrict__ x) {
    const int NF4 = (SEQ * EMBED) / 4;               // float4 per batch
    int i = blockIdx.x * blockDim.x + threadIdx.x;
    if (i >= NF4) return;
    const float4* x4 = reinterpret_cast<const float4*>(x);
    float sx = 0.f, sy = 0.f, sz = 0.f, sw = 0.f;
#pragma unroll
    for (int b = 0; b < BATCH; b++) {
        float4 v = x4[(size_t)b * NF4 + i];
        sx += v.x; sy += v.y; sz += v.z; sw += v.w;
    }
    const float inv = 1.0f / 32.0f;
    float4 r; r.x = sx * inv; r.y = sy * inv; r.z = sz * inv; r.w = sw * inv;
    reinterpret_cast<float4*>(g_xm)[i] = r;
}

// ---------------------------------------------------------------------------
// Kernel 2: SGEMM currents = xm @ W1, f32x2 packed FMA, transposed output.
// 64x64 tile, BK=32, 4x4 micro-tile (packed as 4x2 f32x2), 256 threads.
// ---------------------------------------------------------------------------
#define BM 64
#define BN 64
#define BK 32
#define SA_STRIDE 136   // 128 duplicated floats + 8 pad (bank spread), 16B-aligned

__device__ __forceinline__ void fma2(unsigned long long& d,
                                     unsigned long long a,
                                     unsigned long long b) {
    asm("fma.rn.f32x2 %0, %1, %2, %0;" : "+l"(d) : "l"(a), "l"(b));
}

__global__ void __launch_bounds__(256, 2)
snn_gemm_kernel(const float* __restrict__ W1) {
    __shared__ float sA2[BK][SA_STRIDE];  // a-values duplicated: [k][2*m+d]
    __shared__ float sB[BK][BN];
    __shared__ float sT[BN][68];          // transpose staging [h_local][s_local]

    const int tid = threadIdx.x;
    const int s0 = blockIdx.y * BM;
    const int h0 = blockIdx.x * BN;
    const int ty = tid >> 4;   // 0..15 (m-group)
    const int tx = tid & 15;   // 0..15 (n-group)

    unsigned long long acc2[4][2];
#pragma unroll
    for (int i = 0; i < 4; i++) { acc2[i][0] = 0ull; acc2[i][1] = 0ull; }

    for (int k0 = 0; k0 < EMBED; k0 += BK) {
        // Load A tile (64 s-rows x 32 k), transpose + duplicate into sA2
#pragma unroll
        for (int l = 0; l < 2; l++) {
            int f   = tid + l * 256;      // 0..511
            int row = f >> 3;             // 0..63
            int c4  = f & 7;
            float4 v = *reinterpret_cast<const float4*>(
                &g_xm[(size_t)(s0 + row) * EMBED + k0 + c4 * 4]);
            int kk = c4 * 4;
            *reinterpret_cast<float2*>(&sA2[kk + 0][2 * row]) = make_float2(v.x, v.x);
            *reinterpret_cast<float2*>(&sA2[kk + 1][2 * row]) = make_float2(v.y, v.y);
            *reinterpret_cast<float2*>(&sA2[kk + 2][2 * row]) = make_float2(v.z, v.z);
            *reinterpret_cast<float2*>(&sA2[kk + 3][2 * row]) = make_float2(v.w, v.w);
        }
        // Load B tile (32 k x 64 h)
#pragma unroll
        for (int l = 0; l < 2; l++) {
            int f  = tid + l * 256;
            int r  = f >> 4;
            int c4 = f & 15;
            *reinterpret_cast<float4*>(&sB[r][c4 * 4]) =
                *reinterpret_cast<const float4*>(&W1[(size_t)(k0 + r) * HID + h0 + c4 * 4]);
        }
        __syncthreads();

#pragma unroll
        for (int k = 0; k < BK; k++) {
            // duplicated a pairs: (m0,m0),(m1,m1),(m2,m2),(m3,m3)
            ulonglong2 a01 = *reinterpret_cast<const ulonglong2*>(&sA2[k][ty * 8]);
            ulonglong2 a23 = *reinterpret_cast<const ulonglong2*>(&sA2[k][ty * 8 + 4]);
            // b pairs: (n0,n1),(n2,n3)
            ulonglong2 b   = *reinterpret_cast<const ulonglong2*>(&sB[k][tx * 4]);
            fma2(acc2[0][0], a01.x, b.x); fma2(acc2[0][1], a01.x, b.y);
            fma2(acc2[1][0], a01.y, b.x); fma2(acc2[1][1], a01.y, b.y);
            fma2(acc2[2][0], a23.x, b.x); fma2(acc2[2][1], a23.x, b.y);
            fma2(acc2[3][0], a23.y, b.x); fma2(acc2[3][1], a23.y, b.y);
        }
        __syncthreads();
    }

    // Epilogue: stage transposed tile in smem, write coalesced rows of g_curT
#pragma unroll
    for (int i = 0; i < 4; i++) {
#pragma unroll
        for (int jp = 0; jp < 2; jp++) {
            float2 v = *reinterpret_cast<float2*>(&acc2[i][jp]);
            sT[tx * 4 + jp * 2 + 0][ty * 4 + i] = v.x;
            sT[tx * 4 + jp * 2 + 1][ty * 4 + i] = v.y;
        }
    }
    __syncthreads();
#pragma unroll
    for (int l = 0; l < 4; l++) {
        int f   = tid + l * 256;   // 0..1023
        int row = f >> 4;          // h_local 0..63
        int c4  = f & 15;          // s_local/4
        float4 v = *reinterpret_cast<float4*>(&sT[row][c4 * 4]);
        *reinterpret_cast<float4*>(
            &g_curT[(size_t)(h0 + row) * SEQ + s0 + c4 * 4]) = v;
    }
}

// ---------------------------------------------------------------------------
// Kernel 3: epoch-parallel LIF scan. One block per hidden unit h.
// Post-spike state is always (mem=0, refr=2) -> accumulation restarts at
// t_spike+3. Initial state == "spiked at t=-3". So:
//   1) for every accumulation start a, find next spike time N(a) (parallel)
//   2) pointer-doubling over (jump = N(a)+3, count) to get total spikes.
// ---------------------------------------------------------------------------
#define DECAYF 0.95f

__global__ void __launch_bounds__(1024, 1)
snn_table_kernel(void) {
    __shared__ float    sc[SEQ + 4];   // currents row; reused as Pb in phase 2
    __shared__ unsigned Pa[SEQ + 1];

    const int h   = blockIdx.x;
    const int tid = threadIdx.x;

    // coalesced load of this unit's current stream
    reinterpret_cast<float4*>(sc)[tid] =
        reinterpret_cast<const float4*>(&g_curT[(size_t)h * SEQ])[tid];
    __syncthreads();

    // Phase 1: next-spike table. Start a: mem=0, accumulate until >= 1.
#pragma unroll
    for (int r = 0; r < 4; r++) {
        int a = tid + r * 1024;
        float m = 0.f;
        int t = a;
        while (t < SEQ) {
            m = fmaf(DECAYF, m, sc[t]);
            if (m >= 1.0f) break;
            t++;
        }
        unsigned J, C;
        if (t < SEQ) { J = (unsigned)(t + 3 > SEQ ? SEQ : t + 3); C = 1u; }
        else         { J = (unsigned)SEQ;                         C = 0u; }
        Pa[a] = (C << 13) | J;
    }
    if (tid == 0) Pa[SEQ] = (unsigned)SEQ;  // sentinel: self-loop, count 0
    __syncthreads();

    // Phase 2: pointer doubling (12 rounds covers chain length <= 1366)
    unsigned* Pb = reinterpret_cast<unsigned*>(sc);
    unsigned* srcp = Pa;
    unsigned* dstp = Pb;
#pragma unroll 1
    for (int r = 0; r < 12; r++) {
        for (int a = tid; a <= SEQ; a += 1024) {
            unsigned p = srcp[a];
            unsigned q = srcp[p & 8191u];
            dstp[a] = ((p & ~8191u) + (q & ~8191u)) | (q & 8191u);
        }
        __syncthreads();
        unsigned* tmp = srcp; srcp = dstp; dstp = tmp;
    }
    // 12 rounds (even) -> result back in Pa == srcp
    if (tid == 0) g_cnt[h] = (float)(srcp[0] >> 13);
}

// ---------------------------------------------------------------------------
// Kernel 4: out = (cnt @ W2) / SEQ, broadcast over batch.
// ---------------------------------------------------------------------------
__global__ void snn_out_kernel(const float* __restrict__ W2,
                               float* __restrict__ out) {
    __shared__ float scnt[HID];
    const int tid = threadIdx.x;  // 128
    scnt[tid]       = g_cnt[tid];
    scnt[tid + 128] = g_cnt[tid + 128];
    __syncthreads();
    float a = 0.f;
#pragma unroll 8
    for (int k = 0; k < HID; k++)
        a += scnt[k] * W2[(size_t)k * OUTD + tid];
    a *= (1.0f / (float)SEQ);
#pragma unroll
    for (int b = 0; b < BATCH; b++)
        out[(size_t)b * OUTD + tid] = a;
}

// ---------------------------------------------------------------------------
extern "C" void kernel_launch(void* const* d_in, const int* in_sizes, int n_in,
                              void* d_out, int out_size) {
    const float* x  = (const float*)d_in[0];   // [32][4096][512]
    const float* w1 = (const float*)d_in[1];   // [512][256]
    const float* w2 = (const float*)d_in[2];   // [256][128]
    float* out = (float*)d_out;                // [32][128]

    snn_mean_kernel<<<(SEQ * EMBED / 4 + 255) / 256, 256>>>(x);
    snn_gemm_kernel<<<dim3(HID / BN, SEQ / BM), 256>>>(w1);
    snn_table_kernel<<<HID, 1024>>>();
    snn_out_kernel<<<1, OUTD>>>(w2, out);
}